// round 10
// baseline (speedup 1.0000x reference)
#include <cuda_runtime.h>

#define OPS      40
#define GCOARSE  (OPS * OPS * OPS)
#define DIM      128
#define MAXB     2
#define NPAD     1024   // landmarks per smem tile

// per-point cutoff d^2 > 0.08  ->  dropped weights < exp(-16) ~ 1.1e-7
#define R2_WRP   0.1558f   // (sqrt(0.08) + warp half-diag 0.1118)^2
#define R2_BLK   0.3005f   // (sqrt(0.08) + block half-diag 0.2652)^2

// Coarse displacement field scratch: [b][w0][h0][d0] -> float4 (f0,f1,f2,_)
__device__ float4 g_coarse4[MAXB * GCOARSE];

// ---------------------------------------------------------------------------
// Kernel 1: Gaussian RBF landmark splat, two-level spatial filtering.
// Block = 256 threads covering a w0:4 x h0:8 x d0:8 tile of the 40^3 grid.
// Stage A: deterministic (index-ordered) block-level compaction of landmarks
//          within the block bounding sphere (ballot + warp scan).
// Stage B: per-warp ballot filter over the compacted list, survivors get the
//          full exp + accumulate via broadcast LDS.
// Position components: comp0 <- d0, comp1 <- h0, comp2 <- w0.
// ---------------------------------------------------------------------------
__global__ void __launch_bounds__(256) landmark_kernel(
    const float* __restrict__ coords,   // (B, N, 3)
    const float* __restrict__ offs,     // (B, N, 3)
    int N)
{
    const int b    = blockIdx.z / 5;
    const int dzt  = blockIdx.z % 5;          // d0 tile (of 8)
    const int lane = threadIdx.x & 31;
    const int wi   = threadIdx.x >> 5;        // warp id 0..7

    // lane -> (lw, lh, ld) within the warp's 4(w) x 4(h) x 2(d) sub-tile
    const int lw = lane >> 3;
    const int lh = (lane >> 1) & 3;
    const int ld = lane & 1;

    const int w_base = blockIdx.x * 4;
    const int h_base = blockIdx.y * 8 + ((wi >> 2) << 2);
    const int d_base = dzt * 8 + ((wi & 3) << 1);

    const int w0 = w_base + lw;
    const int h0 = h_base + lh;
    const int d0 = d_base + ld;

    const float step = 2.0f / 39.0f;
    const float p0 = -1.0f + step * (float)d0;
    const float p1 = -1.0f + step * (float)h0;
    const float p2 = -1.0f + step * (float)w0;

    // warp bounding-sphere center
    const float wc0 = -1.0f + step * ((float)d_base + 0.5f);
    const float wc1 = -1.0f + step * ((float)h_base + 1.5f);
    const float wc2 = -1.0f + step * ((float)w_base + 1.5f);

    // block bounding-sphere center (w:4, h:8, d:8 tile)
    const float bc0 = -1.0f + step * ((float)(dzt * 8) + 3.5f);
    const float bc1 = -1.0f + step * ((float)(blockIdx.y * 8) + 3.5f);
    const float bc2 = -1.0f + step * ((float)w_base + 1.5f);

    __shared__ float4 s_cc[NPAD];
    __shared__ float4 s_vv[NPAD];
    __shared__ int    s_cnt[32];
    __shared__ int    s_off[33];

    float sw = 0.0f, a0 = 0.0f, a1 = 0.0f, a2 = 0.0f;

    const float* cb = coords + (size_t)b * N * 3;
    const float* ob = offs   + (size_t)b * N * 3;

    for (int base = 0; base < N; base += NPAD) {
        const int cnt = min(NPAD, N - base);
        const int nch = (cnt + 31) >> 5;      // chunks of 32 in this tile

        // ---- Stage A pass 1: per-chunk survivor counts ----
        for (int c = wi; c < nch; c += 8) {
            const int li = c * 32 + lane;
            bool pass = false;
            if (li < cnt) {
                const int gi = base + li;
                const float cx = cb[gi * 3 + 0] + ob[gi * 3 + 0];
                const float cy = cb[gi * 3 + 1] + ob[gi * 3 + 1];
                const float cz = cb[gi * 3 + 2] + ob[gi * 3 + 2];
                const float dx = bc0 - cx, dy = bc1 - cy, dz = bc2 - cz;
                pass = fmaf(dx, dx, fmaf(dy, dy, dz * dz)) < R2_BLK;
            }
            const unsigned m = __ballot_sync(0xffffffffu, pass);
            if (lane == 0) s_cnt[c] = __popc(m);
        }
        if (threadIdx.x < 32 && threadIdx.x >= nch) s_cnt[threadIdx.x] = 0;
        __syncthreads();

        // ---- exclusive scan of 32 chunk counts (warp 0) ----
        if (wi == 0) {
            int v = s_cnt[lane];
            #pragma unroll
            for (int o = 1; o < 32; o <<= 1) {
                const int t = __shfl_up_sync(0xffffffffu, v, o);
                if (lane >= o) v += t;
            }
            s_off[lane + 1] = v;
            if (lane == 0) s_off[0] = 0;
        }
        __syncthreads();

        const int total = s_off[32];
        const int totp  = (total + 31) & ~31;

        // ---- Stage A pass 2: write compacted survivors (index order) ----
        for (int c = wi; c < nch; c += 8) {
            const int li = c * 32 + lane;
            bool pass = false;
            float cx = 0.f, cy = 0.f, cz = 0.f, vx = 0.f, vy = 0.f, vz = 0.f;
            if (li < cnt) {
                const int gi = base + li;
                const float o0 = ob[gi * 3 + 0];
                const float o1 = ob[gi * 3 + 1];
                const float o2 = ob[gi * 3 + 2];
                cx = cb[gi * 3 + 0] + o0;
                cy = cb[gi * 3 + 1] + o1;
                cz = cb[gi * 3 + 2] + o2;
                vx = -o0; vy = -o1; vz = -o2;
                const float dx = bc0 - cx, dy = bc1 - cy, dz = bc2 - cz;
                pass = fmaf(dx, dx, fmaf(dy, dy, dz * dz)) < R2_BLK;
            }
            const unsigned m = __ballot_sync(0xffffffffu, pass);
            if (pass) {
                const int pos = s_off[c] + __popc(m & ((1u << lane) - 1u));
                s_cc[pos] = make_float4(cx, cy, cz, 0.0f);
                s_vv[pos] = make_float4(vx, vy, vz, 0.0f);
            }
        }
        // sentinel padding to a multiple of 32
        if (threadIdx.x < totp - total) {
            s_cc[total + threadIdx.x] = make_float4(1.0e9f, 1.0e9f, 1.0e9f, 0.0f);
            s_vv[total + threadIdx.x] = make_float4(0.0f, 0.0f, 0.0f, 0.0f);
        }
        __syncthreads();

        // ---- Stage B: per-warp ballot filter + accumulate ----
        for (int ch = 0; ch < totp; ch += 32) {
            const float4 fc = s_cc[ch + lane];
            const float fdx = wc0 - fc.x;
            const float fdy = wc1 - fc.y;
            const float fdz = wc2 - fc.z;
            const float fdd = fmaf(fdx, fdx, fmaf(fdy, fdy, fdz * fdz));
            unsigned m = __ballot_sync(0xffffffffu, fdd < R2_WRP);
            while (m) {
                const int idx = __ffs(m) - 1;
                m &= m - 1;
                const float4 cc = s_cc[ch + idx];   // broadcast LDS
                const float4 vv = s_vv[ch + idx];
                const float ex = p0 - cc.x;
                const float ey = p1 - cc.y;
                const float ez = p2 - cc.z;
                const float d2 = fmaf(ex, ex, fmaf(ey, ey, ez * ez));
                const float w  = __expf(d2 * -200.0f);   // exp(-d2/ALPHA)
                sw += w;
                a0 = fmaf(w, vv.x, a0);
                a1 = fmaf(w, vv.y, a1);
                a2 = fmaf(w, vv.z, a2);
            }
        }
        __syncthreads();
    }

    const float inv = 1.01f / (sw + 0.01f);   // (BETA+1)/(sum+BETA)
    g_coarse4[(size_t)b * GCOARSE + (w0 * OPS + h0) * OPS + d0] =
        make_float4(a0 * inv, a1 * inv, a2 * inv, 0.0f);
}

// ---------------------------------------------------------------------------
// Kernel 2: fused trilinear upsample (40^3 -> 128^3, half-pixel) +
// identity-grid add + branchless trilinear grid_sample (zero padding).
// The (w,h) bilinear part of the coarse interpolation is uniform per block
// (fixed i,j) -> hoisted into a 40-entry shared line; each thread does only
// the d-axis lerp.
// ---------------------------------------------------------------------------
__device__ __forceinline__ void coarse_axis(int o, int& i0, int& i1, float& t)
{
    const float c = fmaxf((float)o * 0.3125f - 0.34375f, 0.0f);
    const float f = floorf(c);
    int a0 = (int)f;
    a0 = a0 > (OPS - 1) ? (OPS - 1) : a0;
    i0 = a0;
    i1 = (a0 + 1 > OPS - 1) ? (OPS - 1) : a0 + 1;
    t = c - (float)a0;
}

__global__ void __launch_bounds__(128) warp_sample_kernel(
    const float* __restrict__ vol,   // (B, 1, 128, 128, 128)
    float* __restrict__ out)         // (B, 1, 128, 128, 128)
{
    const int k = threadIdx.x;       // W index (fastest)
    const int j = blockIdx.x;        // H
    const int i = blockIdx.y;        // D
    const int b = blockIdx.z;

    __shared__ float4 s_f[OPS];      // (w,h)-lerped coarse line over d0

    int w0a, w0b; float tw; coarse_axis(i, w0a, w0b, tw);
    int h0a, h0b; float th; coarse_axis(j, h0a, h0b, th);

    if (k < OPS) {
        const float4* __restrict__ cf = g_coarse4 + (size_t)b * GCOARSE;
        const float4 q00 = __ldg(&cf[(w0a * OPS + h0a) * OPS + k]);
        const float4 q01 = __ldg(&cf[(w0a * OPS + h0b) * OPS + k]);
        const float4 q10 = __ldg(&cf[(w0b * OPS + h0a) * OPS + k]);
        const float4 q11 = __ldg(&cf[(w0b * OPS + h0b) * OPS + k]);
        // h lerp
        const float m0x = fmaf(th, q01.x - q00.x, q00.x);
        const float m0y = fmaf(th, q01.y - q00.y, q00.y);
        const float m0z = fmaf(th, q01.z - q00.z, q00.z);
        const float m1x = fmaf(th, q11.x - q10.x, q10.x);
        const float m1y = fmaf(th, q11.y - q10.y, q10.y);
        const float m1z = fmaf(th, q11.z - q10.z, q10.z);
        // w lerp
        s_f[k] = make_float4(fmaf(tw, m1x - m0x, m0x),
                             fmaf(tw, m1y - m0y, m0y),
                             fmaf(tw, m1z - m0z, m0z), 0.0f);
    }
    __syncthreads();

    int d0a, d0b; float td; coarse_axis(k, d0a, d0b, td);
    const float4 ga = s_f[d0a];
    const float4 gb = s_f[d0b];
    const float f0 = fmaf(td, gb.x - ga.x, ga.x);
    const float f1 = fmaf(td, gb.y - ga.y, ga.y);
    const float f2 = fmaf(td, gb.z - ga.z, ga.z);

    // sample coordinates in voxel units (align_corners=False)
    const float ix = fmaf(f0, 64.0f, fmaf((float)k, 128.0f / 127.0f, -0.5f));
    const float iy = fmaf(f1, 64.0f, fmaf((float)j, 128.0f / 127.0f, -0.5f));
    const float iz = fmaf(f2, 64.0f, fmaf((float)i, 128.0f / 127.0f, -0.5f));

    const float flx = floorf(ix), fly = floorf(iy), flz = floorf(iz);
    const int x0 = (int)flx, y0 = (int)fly, z0 = (int)flz;
    const float fx = ix - flx, fy = iy - fly, fz = iz - flz;

    const float wx0 = ((unsigned)x0       < (unsigned)DIM) ? 1.0f - fx : 0.0f;
    const float wx1 = ((unsigned)(x0 + 1) < (unsigned)DIM) ? fx        : 0.0f;
    const float wy0 = ((unsigned)y0       < (unsigned)DIM) ? 1.0f - fy : 0.0f;
    const float wy1 = ((unsigned)(y0 + 1) < (unsigned)DIM) ? fy        : 0.0f;
    const float wz0 = ((unsigned)z0       < (unsigned)DIM) ? 1.0f - fz : 0.0f;
    const float wz1 = ((unsigned)(z0 + 1) < (unsigned)DIM) ? fz        : 0.0f;

    const int x0c = min(max(x0, 0), DIM - 1), x1c = min(max(x0 + 1, 0), DIM - 1);
    const int y0c = min(max(y0, 0), DIM - 1), y1c = min(max(y0 + 1, 0), DIM - 1);
    const int z0c = min(max(z0, 0), DIM - 1), z1c = min(max(z0 + 1, 0), DIM - 1);

    const float* __restrict__ v = vol + (size_t)b * (DIM * DIM * DIM);

    const int r00 = (z0c << 14) + (y0c << 7);
    const int r01 = (z0c << 14) + (y1c << 7);
    const int r10 = (z1c << 14) + (y0c << 7);
    const int r11 = (z1c << 14) + (y1c << 7);

    const float wz0y0 = wz0 * wy0, wz0y1 = wz0 * wy1;
    const float wz1y0 = wz1 * wy0, wz1y1 = wz1 * wy1;

    float acc;
    acc  = wz0y0 * fmaf(wx1, __ldg(v + r00 + x1c), wx0 * __ldg(v + r00 + x0c));
    acc += wz0y1 * fmaf(wx1, __ldg(v + r01 + x1c), wx0 * __ldg(v + r01 + x0c));
    acc += wz1y0 * fmaf(wx1, __ldg(v + r10 + x1c), wx0 * __ldg(v + r10 + x0c));
    acc += wz1y1 * fmaf(wx1, __ldg(v + r11 + x1c), wx0 * __ldg(v + r11 + x0c));

    out[(((size_t)b * DIM + i) * DIM + j) * DIM + k] = acc;
}

// ---------------------------------------------------------------------------
extern "C" void kernel_launch(void* const* d_in, const int* in_sizes, int n_in,
                              void* d_out, int out_size)
{
    const float* vol    = (const float*)d_in[0];   // (B,1,128,128,128)
    const float* coords = (const float*)d_in[1];   // (B,N,3)
    const float* offs   = (const float*)d_in[2];   // (B,N,3)
    float* out = (float*)d_out;

    const int B = in_sizes[0] / (DIM * DIM * DIM);
    const int N = in_sizes[1] / (B * 3);

    dim3 grid1(OPS / 4, OPS / 8, 5 * B);   // (10, 5, 5B) -> 8 d0-slabs each
    landmark_kernel<<<grid1, 256>>>(coords, offs, N);

    dim3 grid2(DIM, DIM, B);
    warp_sample_kernel<<<grid2, 128>>>(vol, out);
}

// round 11
// speedup vs baseline: 1.0093x; 1.0093x over previous
#include <cuda_runtime.h>

#define OPS      40
#define GCOARSE  (OPS * OPS * OPS)
#define DIM      128
#define MAXB     2
#define NPAD     1024   // landmarks per smem tile

// per-point cutoff d^2 > 0.08  ->  dropped weights < exp(-16) ~ 1.1e-7
#define R2_WRP   0.1558f   // (sqrt(0.08) + warp half-diag 0.1118)^2
#define R2_BLK   0.3005f   // (sqrt(0.08) + block half-diag 0.2652)^2

// Coarse displacement field scratch: [b][w0][h0][d0] -> float4 (f0,f1,f2,_)
__device__ float4 g_coarse4[MAXB * GCOARSE];

// ---------------------------------------------------------------------------
// Kernel 1: Gaussian RBF landmark splat, two-level spatial filtering.
// Block = 256 threads covering a w0:4 x h0:8 x d0:8 tile of the 40^3 grid.
// Stage A: deterministic (index-ordered) block-level compaction of landmarks
//          within the block bounding sphere (ballot + warp scan).
// Stage B: per-warp ballot filter over the compacted list, survivors get the
//          full exp + accumulate via broadcast LDS.
// Position components: comp0 <- d0, comp1 <- h0, comp2 <- w0.
// ---------------------------------------------------------------------------
__global__ void __launch_bounds__(256) landmark_kernel(
    const float* __restrict__ coords,   // (B, N, 3)
    const float* __restrict__ offs,     // (B, N, 3)
    int N)
{
    const int b    = blockIdx.z / 5;
    const int dzt  = blockIdx.z % 5;          // d0 tile (of 8)
    const int lane = threadIdx.x & 31;
    const int wi   = threadIdx.x >> 5;        // warp id 0..7

    // lane -> (lw, lh, ld) within the warp's 4(w) x 4(h) x 2(d) sub-tile
    const int lw = lane >> 3;
    const int lh = (lane >> 1) & 3;
    const int ld = lane & 1;

    const int w_base = blockIdx.x * 4;
    const int h_base = blockIdx.y * 8 + ((wi >> 2) << 2);
    const int d_base = dzt * 8 + ((wi & 3) << 1);

    const int w0 = w_base + lw;
    const int h0 = h_base + lh;
    const int d0 = d_base + ld;

    const float step = 2.0f / 39.0f;
    const float p0 = -1.0f + step * (float)d0;
    const float p1 = -1.0f + step * (float)h0;
    const float p2 = -1.0f + step * (float)w0;

    // warp bounding-sphere center
    const float wc0 = -1.0f + step * ((float)d_base + 0.5f);
    const float wc1 = -1.0f + step * ((float)h_base + 1.5f);
    const float wc2 = -1.0f + step * ((float)w_base + 1.5f);

    // block bounding-sphere center (w:4, h:8, d:8 tile)
    const float bc0 = -1.0f + step * ((float)(dzt * 8) + 3.5f);
    const float bc1 = -1.0f + step * ((float)(blockIdx.y * 8) + 3.5f);
    const float bc2 = -1.0f + step * ((float)w_base + 1.5f);

    __shared__ float4 s_cc[NPAD];
    __shared__ float4 s_vv[NPAD];
    __shared__ int    s_cnt[32];
    __shared__ int    s_off[33];

    float sw = 0.0f, a0 = 0.0f, a1 = 0.0f, a2 = 0.0f;

    const float* cb = coords + (size_t)b * N * 3;
    const float* ob = offs   + (size_t)b * N * 3;

    for (int base = 0; base < N; base += NPAD) {
        const int cnt = min(NPAD, N - base);
        const int nch = (cnt + 31) >> 5;      // chunks of 32 in this tile

        // ---- Stage A pass 1: per-chunk survivor counts ----
        for (int c = wi; c < nch; c += 8) {
            const int li = c * 32 + lane;
            bool pass = false;
            if (li < cnt) {
                const int gi = base + li;
                const float cx = cb[gi * 3 + 0] + ob[gi * 3 + 0];
                const float cy = cb[gi * 3 + 1] + ob[gi * 3 + 1];
                const float cz = cb[gi * 3 + 2] + ob[gi * 3 + 2];
                const float dx = bc0 - cx, dy = bc1 - cy, dz = bc2 - cz;
                pass = fmaf(dx, dx, fmaf(dy, dy, dz * dz)) < R2_BLK;
            }
            const unsigned m = __ballot_sync(0xffffffffu, pass);
            if (lane == 0) s_cnt[c] = __popc(m);
        }
        if (threadIdx.x < 32 && threadIdx.x >= nch) s_cnt[threadIdx.x] = 0;
        __syncthreads();

        // ---- exclusive scan of 32 chunk counts (warp 0) ----
        if (wi == 0) {
            int v = s_cnt[lane];
            #pragma unroll
            for (int o = 1; o < 32; o <<= 1) {
                const int t = __shfl_up_sync(0xffffffffu, v, o);
                if (lane >= o) v += t;
            }
            s_off[lane + 1] = v;
            if (lane == 0) s_off[0] = 0;
        }
        __syncthreads();

        const int total = s_off[32];
        const int totp  = (total + 31) & ~31;

        // ---- Stage A pass 2: write compacted survivors (index order) ----
        for (int c = wi; c < nch; c += 8) {
            const int li = c * 32 + lane;
            bool pass = false;
            float cx = 0.f, cy = 0.f, cz = 0.f, vx = 0.f, vy = 0.f, vz = 0.f;
            if (li < cnt) {
                const int gi = base + li;
                const float o0 = ob[gi * 3 + 0];
                const float o1 = ob[gi * 3 + 1];
                const float o2 = ob[gi * 3 + 2];
                cx = cb[gi * 3 + 0] + o0;
                cy = cb[gi * 3 + 1] + o1;
                cz = cb[gi * 3 + 2] + o2;
                vx = -o0; vy = -o1; vz = -o2;
                const float dx = bc0 - cx, dy = bc1 - cy, dz = bc2 - cz;
                pass = fmaf(dx, dx, fmaf(dy, dy, dz * dz)) < R2_BLK;
            }
            const unsigned m = __ballot_sync(0xffffffffu, pass);
            if (pass) {
                const int pos = s_off[c] + __popc(m & ((1u << lane) - 1u));
                s_cc[pos] = make_float4(cx, cy, cz, 0.0f);
                s_vv[pos] = make_float4(vx, vy, vz, 0.0f);
            }
        }
        // sentinel padding to a multiple of 32
        if (threadIdx.x < totp - total) {
            s_cc[total + threadIdx.x] = make_float4(1.0e9f, 1.0e9f, 1.0e9f, 0.0f);
            s_vv[total + threadIdx.x] = make_float4(0.0f, 0.0f, 0.0f, 0.0f);
        }
        __syncthreads();

        // ---- Stage B: per-warp ballot filter + accumulate ----
        for (int ch = 0; ch < totp; ch += 32) {
            const float4 fc = s_cc[ch + lane];
            const float fdx = wc0 - fc.x;
            const float fdy = wc1 - fc.y;
            const float fdz = wc2 - fc.z;
            const float fdd = fmaf(fdx, fdx, fmaf(fdy, fdy, fdz * fdz));
            unsigned m = __ballot_sync(0xffffffffu, fdd < R2_WRP);
            while (m) {
                const int idx = __ffs(m) - 1;
                m &= m - 1;
                const float4 cc = s_cc[ch + idx];   // broadcast LDS
                const float4 vv = s_vv[ch + idx];
                const float ex = p0 - cc.x;
                const float ey = p1 - cc.y;
                const float ez = p2 - cc.z;
                const float d2 = fmaf(ex, ex, fmaf(ey, ey, ez * ez));
                const float w  = __expf(d2 * -200.0f);   // exp(-d2/ALPHA)
                sw += w;
                a0 = fmaf(w, vv.x, a0);
                a1 = fmaf(w, vv.y, a1);
                a2 = fmaf(w, vv.z, a2);
            }
        }
        __syncthreads();
    }

    const float inv = 1.01f / (sw + 0.01f);   // (BETA+1)/(sum+BETA)
    g_coarse4[(size_t)b * GCOARSE + (w0 * OPS + h0) * OPS + d0] =
        make_float4(a0 * inv, a1 * inv, a2 * inv, 0.0f);
}

// ---------------------------------------------------------------------------
// Kernel 2: fused trilinear upsample (40^3 -> 128^3, half-pixel) +
// identity-grid add + branchless trilinear grid_sample (zero padding).
// The (w,h) bilinear part of the coarse interpolation is uniform per block
// (fixed i,j) -> hoisted into a 40-entry shared line; each thread does only
// the d-axis lerp.
// ---------------------------------------------------------------------------
__device__ __forceinline__ void coarse_axis(int o, int& i0, int& i1, float& t)
{
    const float c = fmaxf((float)o * 0.3125f - 0.34375f, 0.0f);
    const float f = floorf(c);
    int a0 = (int)f;
    a0 = a0 > (OPS - 1) ? (OPS - 1) : a0;
    i0 = a0;
    i1 = (a0 + 1 > OPS - 1) ? (OPS - 1) : a0 + 1;
    t = c - (float)a0;
}

__global__ void __launch_bounds__(128) warp_sample_kernel(
    const float* __restrict__ vol,   // (B, 1, 128, 128, 128)
    float* __restrict__ out)         // (B, 1, 128, 128, 128)
{
    const int k = threadIdx.x;       // W index (fastest)
    const int j = blockIdx.x;        // H
    const int i = blockIdx.y;        // D
    const int b = blockIdx.z;

    __shared__ float4 s_f[OPS];      // (w,h)-lerped coarse line over d0

    int w0a, w0b; float tw; coarse_axis(i, w0a, w0b, tw);
    int h0a, h0b; float th; coarse_axis(j, h0a, h0b, th);

    if (k < OPS) {
        const float4* __restrict__ cf = g_coarse4 + (size_t)b * GCOARSE;
        const float4 q00 = __ldg(&cf[(w0a * OPS + h0a) * OPS + k]);
        const float4 q01 = __ldg(&cf[(w0a * OPS + h0b) * OPS + k]);
        const float4 q10 = __ldg(&cf[(w0b * OPS + h0a) * OPS + k]);
        const float4 q11 = __ldg(&cf[(w0b * OPS + h0b) * OPS + k]);
        // h lerp
        const float m0x = fmaf(th, q01.x - q00.x, q00.x);
        const float m0y = fmaf(th, q01.y - q00.y, q00.y);
        const float m0z = fmaf(th, q01.z - q00.z, q00.z);
        const float m1x = fmaf(th, q11.x - q10.x, q10.x);
        const float m1y = fmaf(th, q11.y - q10.y, q10.y);
        const float m1z = fmaf(th, q11.z - q10.z, q10.z);
        // w lerp
        s_f[k] = make_float4(fmaf(tw, m1x - m0x, m0x),
                             fmaf(tw, m1y - m0y, m0y),
                             fmaf(tw, m1z - m0z, m0z), 0.0f);
    }
    __syncthreads();

    int d0a, d0b; float td; coarse_axis(k, d0a, d0b, td);
    const float4 ga = s_f[d0a];
    const float4 gb = s_f[d0b];
    const float f0 = fmaf(td, gb.x - ga.x, ga.x);
    const float f1 = fmaf(td, gb.y - ga.y, ga.y);
    const float f2 = fmaf(td, gb.z - ga.z, ga.z);

    // sample coordinates in voxel units (align_corners=False)
    const float ix = fmaf(f0, 64.0f, fmaf((float)k, 128.0f / 127.0f, -0.5f));
    const float iy = fmaf(f1, 64.0f, fmaf((float)j, 128.0f / 127.0f, -0.5f));
    const float iz = fmaf(f2, 64.0f, fmaf((float)i, 128.0f / 127.0f, -0.5f));

    const float flx = floorf(ix), fly = floorf(iy), flz = floorf(iz);
    const int x0 = (int)flx, y0 = (int)fly, z0 = (int)flz;
    const float fx = ix - flx, fy = iy - fly, fz = iz - flz;

    const float wx0 = ((unsigned)x0       < (unsigned)DIM) ? 1.0f - fx : 0.0f;
    const float wx1 = ((unsigned)(x0 + 1) < (unsigned)DIM) ? fx        : 0.0f;
    const float wy0 = ((unsigned)y0       < (unsigned)DIM) ? 1.0f - fy : 0.0f;
    const float wy1 = ((unsigned)(y0 + 1) < (unsigned)DIM) ? fy        : 0.0f;
    const float wz0 = ((unsigned)z0       < (unsigned)DIM) ? 1.0f - fz : 0.0f;
    const float wz1 = ((unsigned)(z0 + 1) < (unsigned)DIM) ? fz        : 0.0f;

    const int x0c = min(max(x0, 0), DIM - 1), x1c = min(max(x0 + 1, 0), DIM - 1);
    const int y0c = min(max(y0, 0), DIM - 1), y1c = min(max(y0 + 1, 0), DIM - 1);
    const int z0c = min(max(z0, 0), DIM - 1), z1c = min(max(z0 + 1, 0), DIM - 1);

    const float* __restrict__ v = vol + (size_t)b * (DIM * DIM * DIM);

    const int r00 = (z0c << 14) + (y0c << 7);
    const int r01 = (z0c << 14) + (y1c << 7);
    const int r10 = (z1c << 14) + (y0c << 7);
    const int r11 = (z1c << 14) + (y1c << 7);

    const float wz0y0 = wz0 * wy0, wz0y1 = wz0 * wy1;
    const float wz1y0 = wz1 * wy0, wz1y1 = wz1 * wy1;

    float acc;
    acc  = wz0y0 * fmaf(wx1, __ldg(v + r00 + x1c), wx0 * __ldg(v + r00 + x0c));
    acc += wz0y1 * fmaf(wx1, __ldg(v + r01 + x1c), wx0 * __ldg(v + r01 + x0c));
    acc += wz1y0 * fmaf(wx1, __ldg(v + r10 + x1c), wx0 * __ldg(v + r10 + x0c));
    acc += wz1y1 * fmaf(wx1, __ldg(v + r11 + x1c), wx0 * __ldg(v + r11 + x0c));

    out[(((size_t)b * DIM + i) * DIM + j) * DIM + k] = acc;
}

// ---------------------------------------------------------------------------
extern "C" void kernel_launch(void* const* d_in, const int* in_sizes, int n_in,
                              void* d_out, int out_size)
{
    const float* vol    = (const float*)d_in[0];   // (B,1,128,128,128)
    const float* coords = (const float*)d_in[1];   // (B,N,3)
    const float* offs   = (const float*)d_in[2];   // (B,N,3)
    float* out = (float*)d_out;

    const int B = in_sizes[0] / (DIM * DIM * DIM);
    const int N = in_sizes[1] / (B * 3);

    dim3 grid1(OPS / 4, OPS / 8, 5 * B);   // (10, 5, 5B) -> 8 d0-slabs each
    landmark_kernel<<<grid1, 256>>>(coords, offs, N);

    dim3 grid2(DIM, DIM, B);
    warp_sample_kernel<<<grid2, 128>>>(vol, out);
}

// round 14
// speedup vs baseline: 1.0109x; 1.0016x over previous
#include <cuda_runtime.h>

#define OPS      40
#define GCOARSE  (OPS * OPS * OPS)
#define DIM      128
#define MAXB     2
#define NPAD     1024   // landmarks per smem tile

// per-point cutoff d^2 > 0.08  ->  dropped weights < exp(-16) ~ 1.1e-7
#define R2_WRP   0.1558f   // (sqrt(0.08) + warp half-diag 0.1118)^2
#define R2_BLK   0.3005f   // (sqrt(0.08) + block half-diag 0.2652)^2

// Coarse displacement field scratch: [b][w0][h0][d0] -> float4 (f0,f1,f2,_)
__device__ float4 g_coarse4[MAXB * GCOARSE];

// ---------------------------------------------------------------------------
// Kernel 1: Gaussian RBF landmark splat, two-level spatial filtering.
// Block = 256 threads covering a w0:4 x h0:8 x d0:8 tile of the 40^3 grid.
// Stage A: deterministic (index-ordered) block-level compaction of landmarks
//          within the block bounding sphere (ballot + warp scan); the pass-1
//          ballot masks are cached in smem so pass 2 touches survivors only.
// Stage B: per-warp ballot filter over the compacted list, survivors get the
//          full exp + accumulate via broadcast LDS.
// Position components: comp0 <- d0, comp1 <- h0, comp2 <- w0.
// ---------------------------------------------------------------------------
__global__ void __launch_bounds__(256) landmark_kernel(
    const float* __restrict__ coords,   // (B, N, 3)
    const float* __restrict__ offs,     // (B, N, 3)
    int N)
{
    const int b    = blockIdx.z / 5;
    const int dzt  = blockIdx.z % 5;          // d0 tile (of 8)
    const int lane = threadIdx.x & 31;
    const int wi   = threadIdx.x >> 5;        // warp id 0..7

    // lane -> (lw, lh, ld) within the warp's 4(w) x 4(h) x 2(d) sub-tile
    const int lw = lane >> 3;
    const int lh = (lane >> 1) & 3;
    const int ld = lane & 1;

    const int w_base = blockIdx.x * 4;
    const int h_base = blockIdx.y * 8 + ((wi >> 2) << 2);
    const int d_base = dzt * 8 + ((wi & 3) << 1);

    const int w0 = w_base + lw;
    const int h0 = h_base + lh;
    const int d0 = d_base + ld;

    const float step = 2.0f / 39.0f;
    const float p0 = -1.0f + step * (float)d0;
    const float p1 = -1.0f + step * (float)h0;
    const float p2 = -1.0f + step * (float)w0;

    // warp bounding-sphere center
    const float wc0 = -1.0f + step * ((float)d_base + 0.5f);
    const float wc1 = -1.0f + step * ((float)h_base + 1.5f);
    const float wc2 = -1.0f + step * ((float)w_base + 1.5f);

    // block bounding-sphere center (w:4, h:8, d:8 tile)
    const float bc0 = -1.0f + step * ((float)(dzt * 8) + 3.5f);
    const float bc1 = -1.0f + step * ((float)(blockIdx.y * 8) + 3.5f);
    const float bc2 = -1.0f + step * ((float)w_base + 1.5f);

    __shared__ float4    s_cc[NPAD];
    __shared__ float4    s_vv[NPAD];
    __shared__ unsigned  s_msk[32];
    __shared__ int       s_off[33];

    float sw = 0.0f, a0 = 0.0f, a1 = 0.0f, a2 = 0.0f;

    const float* cb = coords + (size_t)b * N * 3;
    const float* ob = offs   + (size_t)b * N * 3;

    for (int base = 0; base < N; base += NPAD) {
        const int cnt = min(NPAD, N - base);
        const int nch = (cnt + 31) >> 5;      // chunks of 32 in this tile

        // ---- Stage A pass 1: per-chunk survivor ballot masks ----
        for (int c = wi; c < nch; c += 8) {
            const int li = c * 32 + lane;
            bool pass = false;
            if (li < cnt) {
                const int gi = base + li;
                const float cx = cb[gi * 3 + 0] + ob[gi * 3 + 0];
                const float cy = cb[gi * 3 + 1] + ob[gi * 3 + 1];
                const float cz = cb[gi * 3 + 2] + ob[gi * 3 + 2];
                const float dx = bc0 - cx, dy = bc1 - cy, dz = bc2 - cz;
                pass = fmaf(dx, dx, fmaf(dy, dy, dz * dz)) < R2_BLK;
            }
            const unsigned m = __ballot_sync(0xffffffffu, pass);
            if (lane == 0) s_msk[c] = m;
        }
        if (threadIdx.x < 32 && threadIdx.x >= nch) s_msk[threadIdx.x] = 0u;
        __syncthreads();

        // ---- exclusive scan of 32 chunk counts (warp 0) ----
        if (wi == 0) {
            int v = __popc(s_msk[lane]);
            #pragma unroll
            for (int o = 1; o < 32; o <<= 1) {
                const int t = __shfl_up_sync(0xffffffffu, v, o);
                if (lane >= o) v += t;
            }
            s_off[lane + 1] = v;
            if (lane == 0) s_off[0] = 0;
        }
        __syncthreads();

        const int total = s_off[32];
        const int totp  = (total + 31) & ~31;

        // ---- Stage A pass 2: write compacted survivors (index order) ----
        for (int c = wi; c < 32; c += 8) {
            const unsigned m = s_msk[c];
            if ((m >> lane) & 1u) {
                const int gi = base + c * 32 + lane;
                const float o0 = ob[gi * 3 + 0];
                const float o1 = ob[gi * 3 + 1];
                const float o2 = ob[gi * 3 + 2];
                const int pos = s_off[c] + __popc(m & ((1u << lane) - 1u));
                s_cc[pos] = make_float4(cb[gi * 3 + 0] + o0,
                                        cb[gi * 3 + 1] + o1,
                                        cb[gi * 3 + 2] + o2, 0.0f);
                s_vv[pos] = make_float4(-o0, -o1, -o2, 0.0f);
            }
        }
        // sentinel padding to a multiple of 32
        if (threadIdx.x < totp - total) {
            s_cc[total + threadIdx.x] = make_float4(1.0e9f, 1.0e9f, 1.0e9f, 0.0f);
            s_vv[total + threadIdx.x] = make_float4(0.0f, 0.0f, 0.0f, 0.0f);
        }
        __syncthreads();

        // ---- Stage B: per-warp ballot filter + accumulate ----
        for (int ch = 0; ch < totp; ch += 32) {
            const float4 fc = s_cc[ch + lane];
            const float fdx = wc0 - fc.x;
            const float fdy = wc1 - fc.y;
            const float fdz = wc2 - fc.z;
            const float fdd = fmaf(fdx, fdx, fmaf(fdy, fdy, fdz * fdz));
            unsigned m = __ballot_sync(0xffffffffu, fdd < R2_WRP);
            while (m) {
                const int idx = __ffs(m) - 1;
                m &= m - 1;
                const float4 cc = s_cc[ch + idx];   // broadcast LDS
                const float4 vv = s_vv[ch + idx];
                const float ex = p0 - cc.x;
                const float ey = p1 - cc.y;
                const float ez = p2 - cc.z;
                const float d2 = fmaf(ex, ex, fmaf(ey, ey, ez * ez));
                const float w  = __expf(d2 * -200.0f);   // exp(-d2/ALPHA)
                sw += w;
                a0 = fmaf(w, vv.x, a0);
                a1 = fmaf(w, vv.y, a1);
                a2 = fmaf(w, vv.z, a2);
            }
        }
        __syncthreads();
    }

    const float inv = 1.01f / (sw + 0.01f);   // (BETA+1)/(sum+BETA)
    g_coarse4[(size_t)b * GCOARSE + (w0 * OPS + h0) * OPS + d0] =
        make_float4(a0 * inv, a1 * inv, a2 * inv, 0.0f);
}

// ---------------------------------------------------------------------------
// Kernel 2: fused trilinear upsample (40^3 -> 128^3, half-pixel) +
// identity-grid add + trilinear grid_sample (zero padding).
// (w,h) bilinear part of the coarse interpolation hoisted to smem per block.
// Warp-uniform interior fast path: single base pointer, 8 immediate-offset
// taps, 7-lerp trilinear -- no clamps, no predicate weights, no per-tap
// address math. Boundary warps take the branchless slow path.
// ---------------------------------------------------------------------------
__device__ __forceinline__ void coarse_axis(int o, int& i0, int& i1, float& t)
{
    const float c = fmaxf((float)o * 0.3125f - 0.34375f, 0.0f);
    const float f = floorf(c);
    int a0 = (int)f;
    a0 = a0 > (OPS - 1) ? (OPS - 1) : a0;
    i0 = a0;
    i1 = (a0 + 1 > OPS - 1) ? (OPS - 1) : a0 + 1;
    t = c - (float)a0;
}

__global__ void __launch_bounds__(128) warp_sample_kernel(
    const float* __restrict__ vol,   // (B, 1, 128, 128, 128)
    float* __restrict__ out)         // (B, 1, 128, 128, 128)
{
    const int k = threadIdx.x;       // W index (fastest)
    const int j = blockIdx.x;        // H
    const int i = blockIdx.y;        // D
    const int b = blockIdx.z;

    __shared__ float4 s_f[OPS];      // (w,h)-lerped coarse line over d0

    int w0a, w0b; float tw; coarse_axis(i, w0a, w0b, tw);
    int h0a, h0b; float th; coarse_axis(j, h0a, h0b, th);

    if (k < OPS) {
        const float4* __restrict__ cf = g_coarse4 + (size_t)b * GCOARSE;
        const float4 q00 = __ldg(&cf[(w0a * OPS + h0a) * OPS + k]);
        const float4 q01 = __ldg(&cf[(w0a * OPS + h0b) * OPS + k]);
        const float4 q10 = __ldg(&cf[(w0b * OPS + h0a) * OPS + k]);
        const float4 q11 = __ldg(&cf[(w0b * OPS + h0b) * OPS + k]);
        // h lerp
        const float m0x = fmaf(th, q01.x - q00.x, q00.x);
        const float m0y = fmaf(th, q01.y - q00.y, q00.y);
        const float m0z = fmaf(th, q01.z - q00.z, q00.z);
        const float m1x = fmaf(th, q11.x - q10.x, q10.x);
        const float m1y = fmaf(th, q11.y - q10.y, q10.y);
        const float m1z = fmaf(th, q11.z - q10.z, q10.z);
        // w lerp
        s_f[k] = make_float4(fmaf(tw, m1x - m0x, m0x),
                             fmaf(tw, m1y - m0y, m0y),
                             fmaf(tw, m1z - m0z, m0z), 0.0f);
    }
    __syncthreads();

    int d0a, d0b; float td; coarse_axis(k, d0a, d0b, td);
    const float4 ga = s_f[d0a];
    const float4 gb = s_f[d0b];
    const float f0 = fmaf(td, gb.x - ga.x, ga.x);
    const float f1 = fmaf(td, gb.y - ga.y, ga.y);
    const float f2 = fmaf(td, gb.z - ga.z, ga.z);

    // sample coordinates in voxel units (align_corners=False)
    const float ix = fmaf(f0, 64.0f, fmaf((float)k, 128.0f / 127.0f, -0.5f));
    const float iy = fmaf(f1, 64.0f, fmaf((float)j, 128.0f / 127.0f, -0.5f));
    const float iz = fmaf(f2, 64.0f, fmaf((float)i, 128.0f / 127.0f, -0.5f));

    const float flx = floorf(ix), fly = floorf(iy), flz = floorf(iz);
    const int x0 = (int)flx, y0 = (int)fly, z0 = (int)flz;
    const float fx = ix - flx, fy = iy - fly, fz = iz - flz;

    const float* __restrict__ v = vol + (size_t)b * (DIM * DIM * DIM);

    const int interior = ((unsigned)x0 <= 126u) &
                         ((unsigned)y0 <= 126u) &
                         ((unsigned)z0 <= 126u);

    float acc;
    if (__all_sync(0xffffffffu, interior)) {
        // -------- fast path: all 8 taps in bounds, one base pointer --------
        const float* p = v + ((z0 << 14) + (y0 << 7) + x0);
        const float v000 = __ldg(p + 0),             v001 = __ldg(p + 1);
        const float v010 = __ldg(p + 128),           v011 = __ldg(p + 129);
        const float v100 = __ldg(p + 16384),         v101 = __ldg(p + 16385);
        const float v110 = __ldg(p + 16512),         v111 = __ldg(p + 16513);

        const float c00 = fmaf(fx, v001 - v000, v000);
        const float c01 = fmaf(fx, v011 - v010, v010);
        const float c10 = fmaf(fx, v101 - v100, v100);
        const float c11 = fmaf(fx, v111 - v110, v110);
        const float c0  = fmaf(fy, c01 - c00, c00);
        const float c1  = fmaf(fy, c11 - c10, c10);
        acc = fmaf(fz, c1 - c0, c0);
    } else {
        // -------- slow path: branchless zero-padded sampling --------
        const float wx0 = ((unsigned)x0       < (unsigned)DIM) ? 1.0f - fx : 0.0f;
        const float wx1 = ((unsigned)(x0 + 1) < (unsigned)DIM) ? fx        : 0.0f;
        const float wy0 = ((unsigned)y0       < (unsigned)DIM) ? 1.0f - fy : 0.0f;
        const float wy1 = ((unsigned)(y0 + 1) < (unsigned)DIM) ? fy        : 0.0f;
        const float wz0 = ((unsigned)z0       < (unsigned)DIM) ? 1.0f - fz : 0.0f;
        const float wz1 = ((unsigned)(z0 + 1) < (unsigned)DIM) ? fz        : 0.0f;

        const int x0c = min(max(x0, 0), DIM - 1), x1c = min(max(x0 + 1, 0), DIM - 1);
        const int y0c = min(max(y0, 0), DIM - 1), y1c = min(max(y0 + 1, 0), DIM - 1);
        const int z0c = min(max(z0, 0), DIM - 1), z1c = min(max(z0 + 1, 0), DIM - 1);

        const int r00 = (z0c << 14) + (y0c << 7);
        const int r01 = (z0c << 14) + (y1c << 7);
        const int r10 = (z1c << 14) + (y0c << 7);
        const int r11 = (z1c << 14) + (y1c << 7);

        const float wz0y0 = wz0 * wy0, wz0y1 = wz0 * wy1;
        const float wz1y0 = wz1 * wy0, wz1y1 = wz1 * wy1;

        acc  = wz0y0 * fmaf(wx1, __ldg(v + r00 + x1c), wx0 * __ldg(v + r00 + x0c));
        acc += wz0y1 * fmaf(wx1, __ldg(v + r01 + x1c), wx0 * __ldg(v + r01 + x0c));
        acc += wz1y0 * fmaf(wx1, __ldg(v + r10 + x1c), wx0 * __ldg(v + r10 + x0c));
        acc += wz1y1 * fmaf(wx1, __ldg(v + r11 + x1c), wx0 * __ldg(v + r11 + x0c));
    }

    out[(((size_t)b * DIM + i) * DIM + j) * DIM + k] = acc;
}

// ---------------------------------------------------------------------------
extern "C" void kernel_launch(void* const* d_in, const int* in_sizes, int n_in,
                              void* d_out, int out_size)
{
    const float* vol    = (const float*)d_in[0];   // (B,1,128,128,128)
    const float* coords = (const float*)d_in[1];   // (B,N,3)
    const float* offs   = (const float*)d_in[2];   // (B,N,3)
    float* out = (float*)d_out;

    const int B = in_sizes[0] / (DIM * DIM * DIM);
    const int N = in_sizes[1] / (B * 3);

    dim3 grid1(OPS / 4, OPS / 8, 5 * B);   // (10, 5, 5B) -> 8 d0-slabs each
    landmark_kernel<<<grid1, 256>>>(coords, offs, N);

    dim3 grid2(DIM, DIM, B);
    warp_sample_kernel<<<grid2, 128>>>(vol, out);
}